// round 8
// baseline (speedup 1.0000x reference)
#include <cuda_runtime.h>

// SSIM 1-D loss, window 11, sigma 1.5, zero pad 5. B=16,C=32,T=48000 -> 512 rows.
// grid (24, 512), 256 threads/block, 8 outputs/thread (tile 2048).
// SMEM stages only packed (u, v), u=p+t, v=p-t; squares recomputed on the fly.
// Conv: 18 sliding LDS.64/thread, fma.rn.f32x2, 6 distinct symmetric weights.
// Epilogue: SSIM math packed f32x2 across output pairs; scalar fast-divide.
// Block partial -> g_part; last block (atomicInc, self-resetting) reduces.

#define TT     48000
#define NROWS  512
#define TILE   2048
#define TPB    256
#define RPT    8
#define NTILES 24
#define NBLK   (NTILES * NROWS)
#define NL     (TILE + 16)                 // logical [tileStart-8, tileStart+TILE+8)
#define SSZ    (NL + (NL >> 3) + 2)        // pad: phys = i + (i>>3)
#define C1F    1.0e-4f
#define C2F    9.0e-4f
#define CCF    (C1F + C2F)

__device__ float g_part[NBLK];
__device__ unsigned int g_cnt = 0;         // self-resetting via atomicInc wrap

__device__ __forceinline__ unsigned long long pk2(float lo, float hi) {
    unsigned long long r;
    asm("mov.b64 %0, {%1, %2};" : "=l"(r) : "f"(lo), "f"(hi));
    return r;
}
__device__ __forceinline__ void upk2(unsigned long long v, float& lo, float& hi) {
    asm("mov.b64 {%0, %1}, %2;" : "=f"(lo), "=f"(hi) : "l"(v));
}
__device__ __forceinline__ unsigned long long ffma2(unsigned long long a,
                                                    unsigned long long b,
                                                    unsigned long long c) {
    unsigned long long d;
    asm("fma.rn.f32x2 %0, %1, %2, %3;" : "=l"(d) : "l"(a), "l"(b), "l"(c));
    return d;
}

__global__ __launch_bounds__(TPB, 7) void ssim_k(const float* __restrict__ pred,
                                                 const float* __restrict__ tgt,
                                                 float* __restrict__ out) {
    __shared__ unsigned long long sUV[SSZ];    // packed (u, v) only
    __shared__ float  wsum[TPB / 32];
    __shared__ double dsh[TPB / 32];
    __shared__ int    isLast;

    const int tid       = threadIdx.x;
    const int tile      = blockIdx.x;
    const int row       = blockIdx.y;
    const int rowBase   = row * TT;
    const int tileStart = tile * TILE;

    // ---- interior: 8 elems/thread, 2x float4 loads (TT % 8 == 0) ----
    {
        const int src0 = tileStart + tid * RPT;
        float p[RPT], t[RPT];
        if (src0 + RPT - 1 < TT) {
            const float4* pp = reinterpret_cast<const float4*>(pred + rowBase + src0);
            const float4* tp = reinterpret_cast<const float4*>(tgt  + rowBase + src0);
            float4 pa = pp[0], pb = pp[1];
            float4 ta = tp[0], tb = tp[1];
            p[0]=pa.x; p[1]=pa.y; p[2]=pa.z; p[3]=pa.w;
            p[4]=pb.x; p[5]=pb.y; p[6]=pb.z; p[7]=pb.w;
            t[0]=ta.x; t[1]=ta.y; t[2]=ta.z; t[3]=ta.w;
            t[4]=tb.x; t[5]=tb.y; t[6]=tb.z; t[7]=tb.w;
        } else {
#pragma unroll
            for (int e = 0; e < RPT; e++) { p[e] = 0.f; t[e] = 0.f; }
        }
        // logical i0 = 8 + tid*8 (multiple of 8) -> phys base = 9*(tid+1)
        const int ph0 = 9 * (tid + 1);
#pragma unroll
        for (int e = 0; e < RPT; e++) {
            sUV[ph0 + e] = pk2(p[e] + t[e], p[e] - t[e]);
        }
    }
    // ---- halos: logical 0..7 (phys == i) and 2056..2063 (phys = i+257) ----
    if (tid < 8) {
        int src = tileStart - 8 + tid;
        float p = 0.f, t = 0.f;
        if (src >= 0) { p = pred[rowBase + src]; t = tgt[rowBase + src]; }
        sUV[tid] = pk2(p + t, p - t);
    } else if (tid >= 32 && tid < 40) {
        int h = tid - 32;
        int src = tileStart + TILE + h;
        float p = 0.f, t = 0.f;
        if (src < TT) { p = pred[rowBase + src]; t = tgt[rowBase + src]; }
        sUV[2056 + h + 257] = pk2(p + t, p - t);
    }
    __syncthreads();

    // ---- packed Gaussian weights: 6 distinct (symmetric window) ----
    const float Wv[6] = {
        0.001028380f, 0.007598758f, 0.036000773f, 0.109360755f, 0.213005542f,
        0.266011585f
    };
    unsigned long long wp[6];
#pragma unroll
    for (int w = 0; w < 6; w++) wp[w] = pk2(Wv[w], Wv[w]);

    // ---- sliding-window conv: 18 LDS.64, squares on the fly ----
    unsigned long long aUV[RPT], aPQ[RPT];
#pragma unroll
    for (int j = 0; j < RPT; j++) { aUV[j] = 0ull; aPQ[j] = 0ull; }

    const int s = tid * RPT + 3;               // first logical read index
#pragma unroll
    for (int k = 0; k < RPT + 10; k++) {
        int li = s + k;
        unsigned long long quv = sUV[li + (li >> 3)];
        unsigned long long qpq = ffma2(quv, quv, 0ull);   // (u^2, v^2)
#pragma unroll
        for (int j = 0; j < RPT; j++) {
            int w = k - j;
            if (w >= 0 && w < 11) {
                int wi = (w <= 5) ? w : 10 - w;            // compile-time
                aUV[j] = ffma2(quv, wp[wi], aUV[j]);
                aPQ[j] = ffma2(qpq, wp[wi], aPQ[j]);
            }
        }
    }

    // ---- epilogue: packed f32x2 SSIM across output pairs ----
    const unsigned long long halfp  = pk2( 0.5f,  0.5f);
    const unsigned long long nhalfp = pk2(-0.5f, -0.5f);
    const unsigned long long nonep  = pk2(-1.0f, -1.0f);
    const unsigned long long c1p    = pk2(C1F, C1F);
    const unsigned long long ccp    = pk2(CCF, CCF);

    float ssum = 0.0f;
    const int o0 = tileStart + tid * RPT;
#pragma unroll
    for (int jp = 0; jp < RPT; jp += 2) {
        float U0, V0, U1, V1, P0, Q0, P1, Q1;
        upk2(aUV[jp],     U0, V0);
        upk2(aUV[jp + 1], U1, V1);
        upk2(aPQ[jp],     P0, Q0);
        upk2(aPQ[jp + 1], P1, Q1);
        unsigned long long UU = pk2(U0, U1), VV = pk2(V0, V1);
        unsigned long long PP = pk2(P0, P1), QQ = pk2(Q0, Q1);

        unsigned long long U2 = ffma2(UU, UU, 0ull);
        unsigned long long V2 = ffma2(VV, VV, 0ull);
        unsigned long long t1 = ffma2(U2, halfp,  c1p);   // U2/2 + C1
        unsigned long long a2 = ffma2(V2, nhalfp, t1);    // (U2-V2)/2 + C1
        unsigned long long b2 = ffma2(V2, halfp,  t1);    // (U2+V2)/2 + C1
        unsigned long long c2 = ffma2(PP, halfp,
                                 ffma2(QQ, nhalfp, ffma2(a2, nonep, ccp)));
        unsigned long long d2 = ffma2(PP, halfp,
                                 ffma2(QQ, halfp,  ffma2(b2, nonep, ccp)));
        unsigned long long num = ffma2(a2, c2, 0ull);
        unsigned long long den = ffma2(b2, d2, 0ull);

        float n0, n1, e0, e1;
        upk2(num, n0, n1);
        upk2(den, e0, e1);
        float s0 = __fdividef(n0, e0);
        float s1 = __fdividef(n1, e1);
        if (o0 + jp     < TT) ssum += s0;
        if (o0 + jp + 1 < TT) ssum += s1;
    }
    int vc = TT - o0;
    vc = vc < 0 ? 0 : (vc > RPT ? RPT : vc);
    float lsum = (float)vc - ssum;

    // ---- block reduce ----
#pragma unroll
    for (int off = 16; off; off >>= 1)
        lsum += __shfl_down_sync(0xffffffffu, lsum, off);
    const int wid  = tid >> 5;
    const int lane = tid & 31;
    if (lane == 0) wsum[wid] = lsum;
    __syncthreads();

    const int bid = blockIdx.y * gridDim.x + blockIdx.x;
    if (tid < 32) {
        float v2 = (tid < TPB / 32) ? wsum[tid] : 0.0f;
#pragma unroll
        for (int off = 4; off; off >>= 1)
            v2 += __shfl_down_sync(0xffffffffu, v2, off);
        if (tid == 0) {
            g_part[bid] = v2;
            __threadfence();
            unsigned int old = atomicInc(&g_cnt, NBLK - 1u);
            isLast = (old == NBLK - 1u) ? 1 : 0;
        }
    }
    __syncthreads();

    // ---- last block reduces all partials (vectorized reads) ----
    if (isLast) {
        double ds = 0.0;
        const float4* gp4 = reinterpret_cast<const float4*>(g_part);
        for (int k = tid; k < NBLK / 4; k += TPB) {
            float4 q = gp4[k];
            ds += (double)((q.x + q.y) + (q.z + q.w));
        }
#pragma unroll
        for (int off = 16; off; off >>= 1)
            ds += __shfl_down_sync(0xffffffffu, ds, off);
        if (lane == 0) dsh[wid] = ds;
        __syncthreads();
        if (tid == 0) {
            double tot = 0.0;
#pragma unroll
            for (int i = 0; i < TPB / 32; i++) tot += dsh[i];
            out[0] = (float)(tot / (double)((long long)NROWS * TT));
        }
    }
}

extern "C" void kernel_launch(void* const* d_in, const int* in_sizes, int n_in,
                              void* d_out, int out_size) {
    (void)in_sizes; (void)n_in; (void)out_size;
    const float* pred = (const float*)d_in[0];
    const float* tgt  = (const float*)d_in[1];
    dim3 grid(NTILES, NROWS);
    ssim_k<<<grid, TPB>>>(pred, tgt, (float*)d_out);
}

// round 10
// speedup vs baseline: 1.7880x; 1.7880x over previous
#include <cuda_runtime.h>

// SSIM 1-D loss, window 11, sigma 1.5, zero pad 5. B=16,C=32,T=48000 -> 512 rows.
// grid (24, 512), 256 threads/block, 8 outputs/thread (tile 2048).
// SMEM stages only packed (u, v), u=p+t, v=p-t; squares recomputed on the fly.
// Conv: 18 sliding LDS.64/thread, fma.rn.f32x2, 6 distinct symmetric weights.
// Epilogue: SSIM math packed f32x2 across output pairs; scalar fast-divide.
// Block partial -> g_part; last block (atomicInc, self-resetting) reduces.
// NOTE: minBlocksPerMultiprocessor = 6 (40 regs) is the measured sweet spot;
//       7 (32 regs) spills and doubles runtime. Do not raise it.

#define TT     48000
#define NROWS  512
#define TILE   2048
#define TPB    256
#define RPT    8
#define NTILES 24
#define NBLK   (NTILES * NROWS)
#define NL     (TILE + 16)                 // logical [tileStart-8, tileStart+TILE+8)
#define SSZ    (NL + (NL >> 3) + 2)        // pad: phys = i + (i>>3)
#define C1F    1.0e-4f
#define C2F    9.0e-4f
#define CCF    (C1F + C2F)

__device__ float g_part[NBLK];
__device__ unsigned int g_cnt = 0;         // self-resetting via atomicInc wrap

__device__ __forceinline__ unsigned long long pk2(float lo, float hi) {
    unsigned long long r;
    asm("mov.b64 %0, {%1, %2};" : "=l"(r) : "f"(lo), "f"(hi));
    return r;
}
__device__ __forceinline__ void upk2(unsigned long long v, float& lo, float& hi) {
    asm("mov.b64 {%0, %1}, %2;" : "=f"(lo), "=f"(hi) : "l"(v));
}
__device__ __forceinline__ unsigned long long ffma2(unsigned long long a,
                                                    unsigned long long b,
                                                    unsigned long long c) {
    unsigned long long d;
    asm("fma.rn.f32x2 %0, %1, %2, %3;" : "=l"(d) : "l"(a), "l"(b), "l"(c));
    return d;
}

__global__ __launch_bounds__(TPB, 6) void ssim_k(const float* __restrict__ pred,
                                                 const float* __restrict__ tgt,
                                                 float* __restrict__ out) {
    __shared__ unsigned long long sUV[SSZ];    // packed (u, v) only
    __shared__ float  wsum[TPB / 32];
    __shared__ double dsh[TPB / 32];
    __shared__ int    isLast;

    const int tid       = threadIdx.x;
    const int tile      = blockIdx.x;
    const int row       = blockIdx.y;
    const int rowBase   = row * TT;
    const int tileStart = tile * TILE;

    // ---- interior: 8 elems/thread, 2x float4 loads (TT % 8 == 0) ----
    {
        const int src0 = tileStart + tid * RPT;
        float p[RPT], t[RPT];
        if (src0 + RPT - 1 < TT) {
            const float4* pp = reinterpret_cast<const float4*>(pred + rowBase + src0);
            const float4* tp = reinterpret_cast<const float4*>(tgt  + rowBase + src0);
            float4 pa = pp[0], pb = pp[1];
            float4 ta = tp[0], tb = tp[1];
            p[0]=pa.x; p[1]=pa.y; p[2]=pa.z; p[3]=pa.w;
            p[4]=pb.x; p[5]=pb.y; p[6]=pb.z; p[7]=pb.w;
            t[0]=ta.x; t[1]=ta.y; t[2]=ta.z; t[3]=ta.w;
            t[4]=tb.x; t[5]=tb.y; t[6]=tb.z; t[7]=tb.w;
        } else {
#pragma unroll
            for (int e = 0; e < RPT; e++) { p[e] = 0.f; t[e] = 0.f; }
        }
        // logical i0 = 8 + tid*8 (multiple of 8) -> phys base = 9*(tid+1)
        const int ph0 = 9 * (tid + 1);
#pragma unroll
        for (int e = 0; e < RPT; e++) {
            sUV[ph0 + e] = pk2(p[e] + t[e], p[e] - t[e]);
        }
    }
    // ---- halos: logical 0..7 (phys == i) and 2056..2063 (phys = i+257) ----
    if (tid < 8) {
        int src = tileStart - 8 + tid;
        float p = 0.f, t = 0.f;
        if (src >= 0) { p = pred[rowBase + src]; t = tgt[rowBase + src]; }
        sUV[tid] = pk2(p + t, p - t);
    } else if (tid >= 32 && tid < 40) {
        int h = tid - 32;
        int src = tileStart + TILE + h;
        float p = 0.f, t = 0.f;
        if (src < TT) { p = pred[rowBase + src]; t = tgt[rowBase + src]; }
        sUV[2056 + h + 257] = pk2(p + t, p - t);
    }
    __syncthreads();

    // ---- packed Gaussian weights: 6 distinct (symmetric window) ----
    const float Wv[6] = {
        0.001028380f, 0.007598758f, 0.036000773f, 0.109360755f, 0.213005542f,
        0.266011585f
    };
    unsigned long long wp[6];
#pragma unroll
    for (int w = 0; w < 6; w++) wp[w] = pk2(Wv[w], Wv[w]);

    // ---- sliding-window conv: 18 LDS.64, squares on the fly ----
    unsigned long long aUV[RPT], aPQ[RPT];
#pragma unroll
    for (int j = 0; j < RPT; j++) { aUV[j] = 0ull; aPQ[j] = 0ull; }

    const int s = tid * RPT + 3;               // first logical read index
#pragma unroll
    for (int k = 0; k < RPT + 10; k++) {
        int li = s + k;
        unsigned long long quv = sUV[li + (li >> 3)];
        unsigned long long qpq = ffma2(quv, quv, 0ull);   // (u^2, v^2)
#pragma unroll
        for (int j = 0; j < RPT; j++) {
            int w = k - j;
            if (w >= 0 && w < 11) {
                int wi = (w <= 5) ? w : 10 - w;            // compile-time
                aUV[j] = ffma2(quv, wp[wi], aUV[j]);
                aPQ[j] = ffma2(qpq, wp[wi], aPQ[j]);
            }
        }
    }

    // ---- epilogue: packed f32x2 SSIM across output pairs ----
    const unsigned long long halfp  = pk2( 0.5f,  0.5f);
    const unsigned long long nhalfp = pk2(-0.5f, -0.5f);
    const unsigned long long nonep  = pk2(-1.0f, -1.0f);
    const unsigned long long c1p    = pk2(C1F, C1F);
    const unsigned long long ccp    = pk2(CCF, CCF);

    float ssum = 0.0f;
    const int o0 = tileStart + tid * RPT;
#pragma unroll
    for (int jp = 0; jp < RPT; jp += 2) {
        float U0, V0, U1, V1, P0, Q0, P1, Q1;
        upk2(aUV[jp],     U0, V0);
        upk2(aUV[jp + 1], U1, V1);
        upk2(aPQ[jp],     P0, Q0);
        upk2(aPQ[jp + 1], P1, Q1);
        unsigned long long UU = pk2(U0, U1), VV = pk2(V0, V1);
        unsigned long long PP = pk2(P0, P1), QQ = pk2(Q0, Q1);

        unsigned long long U2 = ffma2(UU, UU, 0ull);
        unsigned long long V2 = ffma2(VV, VV, 0ull);
        unsigned long long t1 = ffma2(U2, halfp,  c1p);   // U2/2 + C1
        unsigned long long a2 = ffma2(V2, nhalfp, t1);    // (U2-V2)/2 + C1
        unsigned long long b2 = ffma2(V2, halfp,  t1);    // (U2+V2)/2 + C1
        unsigned long long c2 = ffma2(PP, halfp,
                                 ffma2(QQ, nhalfp, ffma2(a2, nonep, ccp)));
        unsigned long long d2 = ffma2(PP, halfp,
                                 ffma2(QQ, halfp,  ffma2(b2, nonep, ccp)));
        unsigned long long num = ffma2(a2, c2, 0ull);
        unsigned long long den = ffma2(b2, d2, 0ull);

        float n0, n1, e0, e1;
        upk2(num, n0, n1);
        upk2(den, e0, e1);
        float s0 = __fdividef(n0, e0);
        float s1 = __fdividef(n1, e1);
        if (o0 + jp     < TT) ssum += s0;
        if (o0 + jp + 1 < TT) ssum += s1;
    }
    int vc = TT - o0;
    vc = vc < 0 ? 0 : (vc > RPT ? RPT : vc);
    float lsum = (float)vc - ssum;

    // ---- block reduce ----
#pragma unroll
    for (int off = 16; off; off >>= 1)
        lsum += __shfl_down_sync(0xffffffffu, lsum, off);
    const int wid  = tid >> 5;
    const int lane = tid & 31;
    if (lane == 0) wsum[wid] = lsum;
    __syncthreads();

    const int bid = blockIdx.y * gridDim.x + blockIdx.x;
    if (tid < 32) {
        float v2 = (tid < TPB / 32) ? wsum[tid] : 0.0f;
#pragma unroll
        for (int off = 4; off; off >>= 1)
            v2 += __shfl_down_sync(0xffffffffu, v2, off);
        if (tid == 0) {
            g_part[bid] = v2;
            __threadfence();
            unsigned int old = atomicInc(&g_cnt, NBLK - 1u);
            isLast = (old == NBLK - 1u) ? 1 : 0;
        }
    }
    __syncthreads();

    // ---- last block reduces all partials (vectorized reads) ----
    if (isLast) {
        double ds = 0.0;
        const float4* gp4 = reinterpret_cast<const float4*>(g_part);
        for (int k = tid; k < NBLK / 4; k += TPB) {
            float4 q = gp4[k];
            ds += (double)((q.x + q.y) + (q.z + q.w));
        }
#pragma unroll
        for (int off = 16; off; off >>= 1)
            ds += __shfl_down_sync(0xffffffffu, ds, off);
        if (lane == 0) dsh[wid] = ds;
        __syncthreads();
        if (tid == 0) {
            double tot = 0.0;
#pragma unroll
            for (int i = 0; i < TPB / 32; i++) tot += dsh[i];
            out[0] = (float)(tot / (double)((long long)NROWS * TT));
        }
    }
}

extern "C" void kernel_launch(void* const* d_in, const int* in_sizes, int n_in,
                              void* d_out, int out_size) {
    (void)in_sizes; (void)n_in; (void)out_size;
    const float* pred = (const float*)d_in[0];
    const float* tgt  = (const float*)d_in[1];
    dim3 grid(NTILES, NROWS);
    ssim_k<<<grid, TPB>>>(pred, tgt, (float*)d_out);
}